// round 1
// baseline (speedup 1.0000x reference)
#include <cuda_runtime.h>
#include <math.h>

#define NN 2048
#define DD 768
#define HH 12
#define YY 64
#define CC (HH*YY)   // 768

// Scratch (allocation-free rule: __device__ globals)
__device__ float g_Q[HH*NN*YY];           // [h][n][y]
__device__ float g_K[HH*NN*YY];           // [h][n][y]
__device__ float g_partial[HH*(NN/128)];  // 192 per-block LSE partial sums

// ---------------------------------------------------------------------------
// Projection GEMM: Out[h][n][y] = sum_d G[n][d] * W[h*64+y][d]
// BM=BN=128, BK=16, 256 threads, 8x8 micro-tile per thread.
// blockIdx.z selects (Wq -> g_Q) or (Wk -> g_K).
// ---------------------------------------------------------------------------
__global__ void proj_kernel(const float* __restrict__ G,
                            const float* __restrict__ Wq,
                            const float* __restrict__ Wk)
{
    const float* W  = (blockIdx.z == 0) ? Wq : Wk;
    float* Out      = (blockIdx.z == 0) ? g_Q : g_K;

    __shared__ float As[128][17];
    __shared__ float Bs[128][17];

    const int tid = threadIdx.x;           // 0..255
    const int tx  = tid & 15;
    const int ty  = tid >> 4;
    const int n0  = blockIdx.y * 128;
    const int c0  = blockIdx.x * 128;

    float acc[8][8];
    #pragma unroll
    for (int i = 0; i < 8; i++)
        #pragma unroll
        for (int j = 0; j < 8; j++) acc[i][j] = 0.f;

    for (int d0 = 0; d0 < DD; d0 += 16) {
        // cooperative load: 128x16 each of G-tile and W-tile
        #pragma unroll
        for (int i = 0; i < 2; i++) {
            int f  = tid + i * 256;        // float4 index, 0..511
            int r  = f >> 2;
            int c4 = (f & 3) * 4;
            float4 ga = *reinterpret_cast<const float4*>(&G[(size_t)(n0 + r) * DD + d0 + c4]);
            As[r][c4 + 0] = ga.x; As[r][c4 + 1] = ga.y;
            As[r][c4 + 2] = ga.z; As[r][c4 + 3] = ga.w;
            float4 wb = *reinterpret_cast<const float4*>(&W[(size_t)(c0 + r) * DD + d0 + c4]);
            Bs[r][c4 + 0] = wb.x; Bs[r][c4 + 1] = wb.y;
            Bs[r][c4 + 2] = wb.z; Bs[r][c4 + 3] = wb.w;
        }
        __syncthreads();

        #pragma unroll
        for (int kk = 0; kk < 16; kk++) {
            float a[8], b[8];
            #pragma unroll
            for (int i = 0; i < 8; i++) a[i] = As[ty * 8 + i][kk];
            #pragma unroll
            for (int j = 0; j < 8; j++) b[j] = Bs[tx * 8 + j][kk];
            #pragma unroll
            for (int i = 0; i < 8; i++)
                #pragma unroll
                for (int j = 0; j < 8; j++)
                    acc[i][j] = fmaf(a[i], b[j], acc[i][j]);
        }
        __syncthreads();
    }

    // write out in [h][n][y] layout
    #pragma unroll
    for (int i = 0; i < 8; i++) {
        int n = n0 + ty * 8 + i;
        #pragma unroll
        for (int j = 0; j < 8; j++) {
            int c = c0 + tx * 8 + j;
            int h = c >> 6;
            int y = c & 63;
            Out[(size_t)h * (NN * YY) + (size_t)n * YY + y] = acc[i][j];
        }
    }
}

// ---------------------------------------------------------------------------
// Fused scores + online logsumexp.
// One block = 128 q-rows of one head. One thread = one q-row (q in registers).
// K streamed through smem in 64-row chunks; scores in 16-wide sub-chunks.
// ---------------------------------------------------------------------------
__global__ void __launch_bounds__(128) scores_lse_kernel()
{
    __shared__ float Ks[64][64];   // 16 KB
    __shared__ float red[128];

    const int tid = threadIdx.x;
    const int h   = blockIdx.x >> 4;      // 16 q-tiles per head
    const int qt  = blockIdx.x & 15;
    const int row = qt * 128 + tid;

    const float* Qh = g_Q + (size_t)h * NN * YY + (size_t)row * YY;
    const float* Kh = g_K + (size_t)h * NN * YY;

    float4 q4[16];
    #pragma unroll
    for (int i = 0; i < 16; i++)
        q4[i] = *reinterpret_cast<const float4*>(Qh + i * 4);

    float m = -INFINITY;
    float l = 0.f;

    for (int k0 = 0; k0 < NN; k0 += 64) {
        __syncthreads();
        // load K chunk 64x64 (coalesced float4)
        #pragma unroll
        for (int i = 0; i < 8; i++) {
            int f  = tid + i * 128;       // float4 index 0..1023
            int r  = f >> 4;
            int c4 = (f & 15) * 4;
            *reinterpret_cast<float4*>(&Ks[r][c4]) =
                *reinterpret_cast<const float4*>(&Kh[(size_t)(k0 + r) * YY + c4]);
        }
        __syncthreads();

        #pragma unroll
        for (int s16 = 0; s16 < 4; s16++) {
            float acc[16];
            #pragma unroll
            for (int kk = 0; kk < 16; kk++) acc[kk] = 0.f;

            #pragma unroll
            for (int z4 = 0; z4 < 16; z4++) {
                float4 qv = q4[z4];
                #pragma unroll
                for (int kk = 0; kk < 16; kk++) {
                    float4 kv = *reinterpret_cast<const float4*>(&Ks[s16 * 16 + kk][z4 * 4]);
                    float t = acc[kk];
                    t = fmaf(qv.x, kv.x, t);
                    t = fmaf(qv.y, kv.y, t);
                    t = fmaf(qv.z, kv.z, t);
                    t = fmaf(qv.w, kv.w, t);
                    acc[kk] = t;
                }
            }

            // online logsumexp update over these 16 scores
            float cmax = -INFINITY;
            #pragma unroll
            for (int kk = 0; kk < 16; kk++) {
                acc[kk] *= 0.125f;   // beta = 1/sqrt(64)
                cmax = fmaxf(cmax, acc[kk]);
            }
            float m_new = fmaxf(m, cmax);
            l *= __expf(m - m_new);
            #pragma unroll
            for (int kk = 0; kk < 16; kk++)
                l += __expf(acc[kk] - m_new);
            m = m_new;
        }
    }

    float A = m + logf(l);

    // deterministic block reduction
    red[tid] = A;
    __syncthreads();
    #pragma unroll
    for (int s = 64; s > 0; s >>= 1) {
        if (tid < s) red[tid] += red[tid + s];
        __syncthreads();
    }
    if (tid == 0) g_partial[blockIdx.x] = red[0];
}

// ---------------------------------------------------------------------------
// Final deterministic reduction of 192 partials -> scalar out.
// ---------------------------------------------------------------------------
__global__ void finalize_kernel(float* __restrict__ out)
{
    __shared__ float red[256];
    const int tid = threadIdx.x;
    float s = 0.f;
    for (int i = tid; i < HH * (NN / 128); i += 256) s += g_partial[i];
    red[tid] = s;
    __syncthreads();
    #pragma unroll
    for (int st = 128; st > 0; st >>= 1) {
        if (tid < st) red[tid] += red[tid + st];
        __syncthreads();
    }
    if (tid == 0) out[0] = -8.0f * red[0];   // -1/beta = -sqrt(64)
}

extern "C" void kernel_launch(void* const* d_in, const int* in_sizes, int n_in,
                              void* d_out, int out_size)
{
    (void)in_sizes; (void)n_in; (void)out_size;
    const float* g  = (const float*)d_in[0];
    const float* Wq = (const float*)d_in[1];
    const float* Wk = (const float*)d_in[2];
    float* out = (float*)d_out;

    proj_kernel<<<dim3(CC / 128, NN / 128, 2), 256>>>(g, Wq, Wk);
    scores_lse_kernel<<<HH * (NN / 128), 128>>>();
    finalize_kernel<<<1, 256>>>(out);
}

// round 4
// speedup vs baseline: 5.3208x; 5.3208x over previous
#include <cuda_runtime.h>
#include <cuda_bf16.h>
#include <cstdint>
#include <math.h>

#define NN 2048
#define DD 768
#define HH 12
#define YY 64

// ---------------------------------------------------------------------------
// Scratch (__device__ globals; no allocation allowed)
// ---------------------------------------------------------------------------
__device__ __nv_bfloat16 g_gb [NN * DD];       // g in bf16
__device__ __nv_bfloat16 g_Wqb[HH * YY * DD];  // Wq in bf16
__device__ __nv_bfloat16 g_Wkb[HH * YY * DD];  // Wk in bf16
__device__ __nv_bfloat16 g_Q[HH * NN * YY];    // [h][n][y], pre-scaled by beta
__device__ __nv_bfloat16 g_K[HH * NN * YY];    // [h][n][y]
__device__ float g_partial[HH * (NN / 128)];   // 192 per-block LSE partials

// ---------------------------------------------------------------------------
// Helpers (standard sm_80+ features: ldmatrix / mma.sync / cp.async)
// ---------------------------------------------------------------------------
__device__ __forceinline__ uint32_t smem_u32(const void* p) {
    uint32_t a;
    asm("{ .reg .u64 t; cvta.to.shared.u64 t, %1; cvt.u32.u64 %0, t; }" : "=r"(a) : "l"(p));
    return a;
}

__device__ __forceinline__ void cpa16(uint32_t dst, const void* src) {
    asm volatile("cp.async.cg.shared.global [%0], [%1], 16;" :: "r"(dst), "l"(src));
}
#define CP_COMMIT() asm volatile("cp.async.commit_group;" ::: "memory")
#define CP_WAIT(n)  asm volatile("cp.async.wait_group %0;" :: "n"(n) : "memory")

__device__ __forceinline__ void ldsm4(uint32_t& r0, uint32_t& r1, uint32_t& r2, uint32_t& r3,
                                      uint32_t addr) {
    asm volatile("ldmatrix.sync.aligned.m8n8.x4.shared.b16 {%0,%1,%2,%3}, [%4];"
                 : "=r"(r0), "=r"(r1), "=r"(r2), "=r"(r3) : "r"(addr));
}

__device__ __forceinline__ void mma16816(float* c, const uint32_t* a, uint32_t b0, uint32_t b1) {
    asm volatile(
        "mma.sync.aligned.m16n8k16.row.col.f32.bf16.bf16.f32 "
        "{%0,%1,%2,%3}, {%4,%5,%6,%7}, {%8,%9}, {%0,%1,%2,%3};"
        : "+f"(c[0]), "+f"(c[1]), "+f"(c[2]), "+f"(c[3])
        : "r"(a[0]), "r"(a[1]), "r"(a[2]), "r"(a[3]), "r"(b0), "r"(b1));
}

__device__ __forceinline__ uint32_t bf16x2(float hi, float lo) {
    uint32_t r;
    asm("cvt.rn.bf16x2.f32 %0, %1, %2;" : "=r"(r) : "f"(hi), "f"(lo));
    return r;
}

// ---------------------------------------------------------------------------
// Convert f32 inputs -> bf16 globals. One thread = 8 elements (16B out).
// ---------------------------------------------------------------------------
#define NG8 (NN * DD / 8)          // 196608
#define NW8 (HH * YY * DD / 8)     // 73728

__global__ void __launch_bounds__(256) conv_kernel(const float* __restrict__ g,
                                                   const float* __restrict__ wq,
                                                   const float* __restrict__ wk)
{
    int i = blockIdx.x * 256 + threadIdx.x;
    const float* src;
    __nv_bfloat16* dst;
    int j;
    if (i < NG8)                { src = g;  dst = g_gb;  j = i; }
    else if (i < NG8 + NW8)     { src = wq; dst = g_Wqb; j = i - NG8; }
    else if (i < NG8 + 2 * NW8) { src = wk; dst = g_Wkb; j = i - NG8 - NW8; }
    else return;
    float4 v0 = *reinterpret_cast<const float4*>(src + (size_t)j * 8);
    float4 v1 = *reinterpret_cast<const float4*>(src + (size_t)j * 8 + 4);
    uint4 o;
    o.x = bf16x2(v0.y, v0.x);
    o.y = bf16x2(v0.w, v0.z);
    o.z = bf16x2(v1.y, v1.x);
    o.w = bf16x2(v1.w, v1.z);
    *reinterpret_cast<uint4*>(dst + (size_t)j * 8) = o;
}

// ---------------------------------------------------------------------------
// Projection: Out[c][n] for c = h*64+y.  Out = g . W^T.
// CTA tile 128n x 128c, k-chunk 32 (pitch 80B, conflict-free ldmatrix).
// grid (6, 16, 2); 256 threads (8 warps: 4m x 2n); warp tile 32 x 64.
// Dynamic smem: 4 * 10240 = 40960 B (< 48KB, no attribute call needed).
// ---------------------------------------------------------------------------
#define PROWB 80
#define P_TILE (128 * PROWB)                // 10240 B
#define P_SMEM (4 * P_TILE)                 // 40960 B

__global__ void __launch_bounds__(256) proj_kernel()
{
    extern __shared__ char sm[];
    const uint32_t sb = smem_u32(sm);
    const int tid = threadIdx.x, lane = tid & 31, wid = tid >> 5;
    const int wm = wid & 3, wn = wid >> 2;
    const int c0 = blockIdx.x * 128, n0 = blockIdx.y * 128;
    const __nv_bfloat16* __restrict__ A = g_gb;
    const __nv_bfloat16* __restrict__ B = blockIdx.z ? g_Wkb : g_Wqb;
    __nv_bfloat16* __restrict__ Out = blockIdx.z ? g_K : g_Q;
    const float scale = blockIdx.z ? 1.0f : 0.125f;

    const uint32_t Ab[2] = { sb,              sb + P_TILE };
    const uint32_t Bb[2] = { sb + 2 * P_TILE, sb + 3 * P_TILE };

    // 128 rows x 2 granules(16B) per tile = 512 granules -> 2 per thread
    auto load_chunk = [&](int ch) {
        const int d0 = ch * 32;
        const uint32_t abuf = Ab[ch & 1], bbuf = Bb[ch & 1];
        #pragma unroll
        for (int i = 0; i < 2; i++) {
            int gi = tid + i * 256;
            int r = gi >> 2, c = gi & 3;
            cpa16(abuf + r * PROWB + c * 16, A + (size_t)(n0 + r) * DD + d0 + c * 8);
            cpa16(bbuf + r * PROWB + c * 16, B + (size_t)(c0 + r) * DD + d0 + c * 8);
        }
    };

    float acc[2][8][4];
    #pragma unroll
    for (int mt = 0; mt < 2; mt++)
        #pragma unroll
        for (int nt = 0; nt < 8; nt++)
            #pragma unroll
            for (int k = 0; k < 4; k++) acc[mt][nt][k] = 0.f;

    const int lr = lane & 7;
    const uint32_t aoff = (uint32_t)((wm * 32 + lr + ((lane >> 3) & 1) * 8) * PROWB
                                     + ((lane >> 4) & 1) * 16);
    const uint32_t boff = (uint32_t)((wn * 64 + lr + ((lane >> 4) & 1) * 8) * PROWB
                                     + ((lane >> 3) & 1) * 16);

    load_chunk(0); CP_COMMIT();

    for (int ch = 0; ch < 24; ch++) {
        if (ch < 23) { load_chunk(ch + 1); CP_COMMIT(); CP_WAIT(1); }
        else CP_WAIT(0);
        __syncthreads();

        const uint32_t abase = Ab[ch & 1] + aoff;
        const uint32_t bbase = Bb[ch & 1] + boff;
        #pragma unroll
        for (int ks = 0; ks < 2; ks++) {
            uint32_t a0[4], a1[4];
            ldsm4(a0[0], a0[1], a0[2], a0[3], abase + ks * 32);
            ldsm4(a1[0], a1[1], a1[2], a1[3], abase + 16 * PROWB + ks * 32);
            #pragma unroll
            for (int ntp = 0; ntp < 4; ntp++) {
                uint32_t b0, b1, b2, b3;
                ldsm4(b0, b1, b2, b3, bbase + ntp * 16 * PROWB + ks * 32);
                mma16816(acc[0][2 * ntp],     a0, b0, b1);
                mma16816(acc[1][2 * ntp],     a1, b0, b1);
                mma16816(acc[0][2 * ntp + 1], a0, b2, b3);
                mma16816(acc[1][2 * ntp + 1], a1, b2, b3);
            }
        }
        __syncthreads();
    }

    // Epilogue: write bf16, layout [h][n][y]; each warp-col covers one head
    const int h = (c0 >> 6) + wn;
    const int rbase = n0 + wm * 32 + (lane >> 2);
    #pragma unroll
    for (int mt = 0; mt < 2; mt++) {
        #pragma unroll
        for (int nt = 0; nt < 8; nt++) {
            const int y = nt * 8 + (lane & 3) * 2;
            const int n1 = rbase + mt * 16;
            uint32_t p0 = bf16x2(acc[mt][nt][1] * scale, acc[mt][nt][0] * scale);
            uint32_t p1 = bf16x2(acc[mt][nt][3] * scale, acc[mt][nt][2] * scale);
            *reinterpret_cast<uint32_t*>(&Out[((size_t)h * NN + n1) * YY + y])     = p0;
            *reinterpret_cast<uint32_t*>(&Out[((size_t)h * NN + n1 + 8) * YY + y]) = p1;
        }
    }
}

// ---------------------------------------------------------------------------
// Fused scores + LSE. CTA per (qtile 128, head). 8 warps x 16 q-rows.
// Q staged through buffer 0 once -> register fragments; K ping-pongs through
// both buffers. Threshold-pruned online logsumexp in the epilogue.
// Dynamic smem: 2 * 18432 + 256 = 37120 B (< 48KB).
// ---------------------------------------------------------------------------
#define ROWB 144
#define S_TILE (128 * ROWB)                 // 18432 B
#define S_RED  (2 * S_TILE)
#define S_SMEM (S_RED + 64 * 4)

__global__ void __launch_bounds__(256) scores_kernel()
{
    extern __shared__ char sm[];
    const uint32_t sb = smem_u32(sm);
    const int tid = threadIdx.x, lane = tid & 31, wid = tid >> 5;
    const int h = blockIdx.y, qt = blockIdx.x;

    const __nv_bfloat16* __restrict__ Qsrc = g_Q + ((size_t)h * NN + qt * 128) * YY;
    const __nv_bfloat16* __restrict__ Ksrc = g_K + (size_t)h * NN * YY;

    // 1024 granules per 128x64 tile -> 4 per thread
    auto load_q = [&]() {
        #pragma unroll
        for (int i = 0; i < 4; i++) {
            int gi = tid + i * 256;
            int r = gi >> 3, c = gi & 7;
            cpa16(sb + r * ROWB + c * 16, Qsrc + (size_t)r * YY + c * 8);
        }
    };
    auto load_k = [&](int ch) {
        const int k0 = ch * 128;
        const uint32_t buf = sb + (ch & 1) * S_TILE;
        #pragma unroll
        for (int i = 0; i < 4; i++) {
            int gi = tid + i * 256;
            int r = gi >> 3, c = gi & 7;
            cpa16(buf + r * ROWB + c * 16, Ksrc + (size_t)(k0 + r) * YY + c * 8);
        }
    };

    const int lr = lane & 7;
    const uint32_t aoff = (uint32_t)((wid * 16 + lr + ((lane >> 3) & 1) * 8) * ROWB
                                     + ((lane >> 4) & 1) * 16);
    const uint32_t boff = (uint32_t)((lr + ((lane >> 4) & 1) * 8) * ROWB
                                     + ((lane >> 3) & 1) * 16);

    // Stage Q through buffer 0, pull fragments into registers, then free it.
    load_q(); CP_COMMIT(); CP_WAIT(0);
    __syncthreads();
    uint32_t aR[4][4];
    #pragma unroll
    for (int ks = 0; ks < 4; ks++)
        ldsm4(aR[ks][0], aR[ks][1], aR[ks][2], aR[ks][3], sb + aoff + ks * 32);
    __syncthreads();

    load_k(0); CP_COMMIT();

    float m0 = -INFINITY, l0 = 0.f;   // row a = lane>>2
    float m1 = -INFINITY, l1 = 0.f;   // row b = (lane>>2) + 8

    auto upd = [](float v, float& m, float& l) {
        if (v > m) { l = l * __expf(m - v) + 1.0f; m = v; }
        else if (v > m - 16.0f) { l += __expf(v - m); }
    };

    for (int ch = 0; ch < 16; ch++) {
        if (ch < 15) { load_k(ch + 1); CP_COMMIT(); CP_WAIT(1); }
        else CP_WAIT(0);
        __syncthreads();

        const uint32_t bbase = sb + (ch & 1) * S_TILE + boff;
        #pragma unroll
        for (int ntp = 0; ntp < 8; ntp++) {
            float acc[8];
            #pragma unroll
            for (int j = 0; j < 8; j++) acc[j] = 0.f;
            #pragma unroll
            for (int ks = 0; ks < 4; ks++) {
                uint32_t b0, b1, b2, b3;
                ldsm4(b0, b1, b2, b3, bbase + ntp * 16 * ROWB + ks * 32);
                mma16816(acc,     aR[ks], b0, b1);
                mma16816(acc + 4, aR[ks], b2, b3);
            }
            // rows: acc[0],[1],[4],[5] -> row a ; acc[2],[3],[6],[7] -> row b
            float ca = fmaxf(fmaxf(acc[0], acc[1]), fmaxf(acc[4], acc[5]));
            float cb = fmaxf(fmaxf(acc[2], acc[3]), fmaxf(acc[6], acc[7]));
            if (ca > m0 - 16.0f) {
                upd(acc[0], m0, l0); upd(acc[1], m0, l0);
                upd(acc[4], m0, l0); upd(acc[5], m0, l0);
            }
            if (cb > m1 - 16.0f) {
                upd(acc[2], m1, l1); upd(acc[3], m1, l1);
                upd(acc[6], m1, l1); upd(acc[7], m1, l1);
            }
        }
        __syncthreads();
    }

    // combine the 4 lanes of each quad-row
    #pragma unroll
    for (int off = 1; off <= 2; off <<= 1) {
        float mo = __shfl_xor_sync(0xffffffffu, m0, off);
        float lo = __shfl_xor_sync(0xffffffffu, l0, off);
        float mm = fmaxf(m0, mo);
        l0 = l0 * __expf(m0 - mm) + lo * __expf(mo - mm);
        m0 = mm;
        mo = __shfl_xor_sync(0xffffffffu, m1, off);
        lo = __shfl_xor_sync(0xffffffffu, l1, off);
        mm = fmaxf(m1, mo);
        l1 = l1 * __expf(m1 - mm) + lo * __expf(mo - mm);
        m1 = mm;
    }

    float* red = reinterpret_cast<float*>(sm + S_RED);
    if ((lane & 3) == 0) {
        float A0 = m0 + logf(l0);
        float A1 = m1 + logf(l1);
        red[wid * 8 + (lane >> 2)] = A0 + A1;
    }
    __syncthreads();
    if (tid < 32) {
        float s = red[tid] + red[tid + 32];
        #pragma unroll
        for (int off = 16; off > 0; off >>= 1)
            s += __shfl_xor_sync(0xffffffffu, s, off);
        if (tid == 0) g_partial[h * 16 + qt] = s;
    }
}

// ---------------------------------------------------------------------------
// Final reduction: out = -8 * sum(partials)
// ---------------------------------------------------------------------------
__global__ void finalize_kernel(float* __restrict__ out)
{
    __shared__ float red[256];
    const int tid = threadIdx.x;
    float s = 0.f;
    for (int i = tid; i < HH * (NN / 128); i += 256) s += g_partial[i];
    red[tid] = s;
    __syncthreads();
    #pragma unroll
    for (int st = 128; st > 0; st >>= 1) {
        if (tid < st) red[tid] += red[tid + st];
        __syncthreads();
    }
    if (tid == 0) out[0] = -8.0f * red[0];
}

extern "C" void kernel_launch(void* const* d_in, const int* in_sizes, int n_in,
                              void* d_out, int out_size)
{
    (void)in_sizes; (void)n_in; (void)out_size;
    const float* g  = (const float*)d_in[0];
    const float* Wq = (const float*)d_in[1];
    const float* Wk = (const float*)d_in[2];
    float* out = (float*)d_out;

    const int convN = NG8 + 2 * NW8;
    conv_kernel<<<(convN + 255) / 256, 256>>>(g, Wq, Wk);
    proj_kernel<<<dim3(6, 16, 2), 256, P_SMEM>>>();
    scores_kernel<<<dim3(16, HH), 256, S_SMEM>>>();
    finalize_kernel<<<1, 256>>>(out);
}